// round 4
// baseline (speedup 1.0000x reference)
#include <cuda_runtime.h>

// LSTMBrain: 2-layer LSTM (hidden=3) over [B=4096, T=2048], dense head 3->1.
// Round 4: 6-lane groups (no duplicate lanes): lane role r = lane%6,
//   r=0..2 -> layer-1 unit r, r=3..5 -> layer-2 unit r-3. 5 elements per warp
//   (lanes 30,31 idle). Each lane carries TWO elements (eA, eB=eA+pairs),
//   interleaved each iteration for in-warp ILP -> 412 warps in 103 blocks of
//   128 threads = at most ONE warp per SMSP (no cross-warp MUFU contention).
// MUFU reduction: rcp(d_i * d_f) pairing within an element (off critical path),
// o-gate rcp paired ACROSS the two elements. 17 MUFU / iter (was 24).
// Layers software-pipelined as before (L2 lags L1 by one step).

#define FULLM 0xFFFFFFFFu
#define LOG2E 1.4426950408889634f

__device__ __forceinline__ float fast_rcp(float x) {
    float r; asm("rcp.approx.f32 %0, %1;" : "=f"(r) : "f"(x)); return r;
}
__device__ __forceinline__ float fast_ex2(float x) {
    float r; asm("ex2.approx.f32 %0, %1;" : "=f"(r) : "f"(x)); return r;
}

__global__ void __launch_bounds__(128, 1) lstm2_dual_kernel(
    const float* __restrict__ state,
    const float* __restrict__ W1, const float* __restrict__ U1, const float* __restrict__ b1,
    const float* __restrict__ W2, const float* __restrict__ U2, const float* __restrict__ b2,
    const float* __restrict__ Wd, const float* __restrict__ bd,
    float* __restrict__ out, int B, int T, int pairs)
{
    const int warpId = (blockIdx.x * blockDim.x + threadIdx.x) >> 5;
    const int lane   = threadIdx.x & 31;
    const int role   = lane % 6;            // 0..2: L1 unit, 3..5: L2 unit
    const int grp    = lane / 6;            // 0..4 valid; 5 = idle lanes 30,31
    const int gbase  = lane - role;         // first lane of this 6-lane group
    const bool isL2  = (role >= 3);
    const int  u     = isL2 ? (role - 3) : role;

    const int  eA   = warpId * 5 + grp;
    const bool actA = (grp < 5) && (eA < pairs);
    const int  eB   = eA + pairs;
    const bool actB = actA && (eB < B);
    const int  eAc  = actA ? eA : 0;        // clamped for safe loads
    const int  eBc  = actB ? eB : 0;

    // ---- per-lane coefficients, pre-scaled into the ex2 domain ----
    // gate g = 0:i 1:f 2:g(tanh) 3:o ; weight column = g*3 + u
    // sigma(y) = rcp(1 + ex2(-log2e*y)); tanh(y) = 2*rcp(1 + ex2(-2log2e*y)) - 1
    float A[4], bias[4], Bk[3][4], Ck[3][4];
#pragma unroll
    for (int g = 0; g < 4; ++g) {
        const int col = g * 3 + u;
        const float sc = (g == 2) ? (-2.0f * LOG2E) : (-LOG2E);
        if (isL2) {
            A[g]    = 0.0f;
            bias[g] = __ldg(b2 + col) * sc;
#pragma unroll
            for (int k = 0; k < 3; ++k) {
                Bk[k][g] = __ldg(W2 + k * 12 + col) * sc;   // multiplies s1 bcast
                Ck[k][g] = __ldg(U2 + k * 12 + col) * sc;   // multiplies h2 bcast
            }
        } else {
            A[g]    = __ldg(W1 + col) * sc;
            bias[g] = __ldg(b1 + col) * sc;
#pragma unroll
            for (int k = 0; k < 3; ++k) {
                Bk[k][g] = __ldg(U1 + k * 12 + col) * sc;   // multiplies s1 bcast
                Ck[k][g] = 0.0f;
            }
        }
    }

    const float* rowA = state + (size_t)eAc * (size_t)T;
    const float* rowB = state + (size_t)eBc * (size_t)T;

    // per-element state (cell kept in the -2log2e-scaled domain)
    float ccA = 0.f, ccB = 0.f;
    float outA = 0.f, outB = 0.f;
    float SA0 = 0.f, SA1 = 0.f, SA2 = 0.f, HA0 = 0.f, HA1 = 0.f, HA2 = 0.f;
    float SB0 = 0.f, SB1 = 0.f, SB2 = 0.f, HB0 = 0.f, HB1 = 0.f, HB2 = 0.f;

    // STEP: produces updated scaled cell cc, o-gate denominator d3, tanh(c) tc.
#define STEP(xv, S0, S1, S2, H0, H1, H2, cc, d3o, tco)                      \
    do {                                                                    \
        float z0 = fmaf(A[0], (xv), bias[0]);                               \
        float z1 = fmaf(A[1], (xv), bias[1]);                               \
        float z2 = fmaf(A[2], (xv), bias[2]);                               \
        float z3 = fmaf(A[3], (xv), bias[3]);                               \
        z0 = fmaf(Bk[0][0], (S0), z0); z1 = fmaf(Bk[0][1], (S0), z1);       \
        z2 = fmaf(Bk[0][2], (S0), z2); z3 = fmaf(Bk[0][3], (S0), z3);       \
        z0 = fmaf(Bk[1][0], (S1), z0); z1 = fmaf(Bk[1][1], (S1), z1);       \
        z2 = fmaf(Bk[1][2], (S1), z2); z3 = fmaf(Bk[1][3], (S1), z3);       \
        z0 = fmaf(Bk[2][0], (S2), z0); z1 = fmaf(Bk[2][1], (S2), z1);       \
        z2 = fmaf(Bk[2][2], (S2), z2); z3 = fmaf(Bk[2][3], (S2), z3);       \
        z0 = fmaf(Ck[0][0], (H0), z0); z1 = fmaf(Ck[0][1], (H0), z1);       \
        z2 = fmaf(Ck[0][2], (H0), z2); z3 = fmaf(Ck[0][3], (H0), z3);       \
        z0 = fmaf(Ck[1][0], (H1), z0); z1 = fmaf(Ck[1][1], (H1), z1);       \
        z2 = fmaf(Ck[1][2], (H1), z2); z3 = fmaf(Ck[1][3], (H1), z3);       \
        z0 = fmaf(Ck[2][0], (H2), z0); z1 = fmaf(Ck[2][1], (H2), z1);       \
        z2 = fmaf(Ck[2][2], (H2), z2); z3 = fmaf(Ck[2][3], (H2), z3);       \
        const float d0 = 1.0f + fast_ex2(z0);                               \
        const float d1 = 1.0f + fast_ex2(z1);                               \
        const float d2 = 1.0f + fast_ex2(z2);                               \
        (d3o) = 1.0f + fast_ex2(z3);                                        \
        const float r01 = fast_rcp(d0 * d1);                                \
        const float si  = r01 * d1;   /* 1/d0 */                            \
        const float sf  = r01 * d0;   /* 1/d1 */                            \
        const float rg  = fast_rcp(d2);                                     \
        const float tgs = fmaf(-4.0f * LOG2E, rg, 2.0f * LOG2E);            \
        (cc) = fmaf(sf, (cc), si * tgs);                                    \
        const float rc = fast_rcp(1.0f + fast_ex2((cc)));                   \
        (tco) = fmaf(2.0f, rc, -1.0f);                                      \
    } while (0)

    // one iteration: step both elements, shared o-gate rcp, broadcasts
#define ITER(xa, xb)                                                        \
    do {                                                                    \
        float d3A, tcA, d3B, tcB;                                           \
        STEP((xa), SA0, SA1, SA2, HA0, HA1, HA2, ccA, d3A, tcA);            \
        STEP((xb), SB0, SB1, SB2, HB0, HB1, HB2, ccB, d3B, tcB);            \
        const float r3 = fast_rcp(d3A * d3B);                               \
        outA = (r3 * d3B) * tcA;                                            \
        outB = (r3 * d3A) * tcB;                                            \
    } while (0)

#define BCAST()                                                             \
    do {                                                                    \
        SA0 = __shfl_sync(FULLM, outA, gbase + 0);                          \
        SA1 = __shfl_sync(FULLM, outA, gbase + 1);                          \
        SA2 = __shfl_sync(FULLM, outA, gbase + 2);                          \
        HA0 = __shfl_sync(FULLM, outA, gbase + 3);                          \
        HA1 = __shfl_sync(FULLM, outA, gbase + 4);                          \
        HA2 = __shfl_sync(FULLM, outA, gbase + 5);                          \
        SB0 = __shfl_sync(FULLM, outB, gbase + 0);                          \
        SB1 = __shfl_sync(FULLM, outB, gbase + 1);                          \
        SB2 = __shfl_sync(FULLM, outB, gbase + 2);                          \
        HB0 = __shfl_sync(FULLM, outB, gbase + 3);                          \
        HB1 = __shfl_sync(FULLM, outB, gbase + 4);                          \
        HB2 = __shfl_sync(FULLM, outB, gbase + 5);                          \
    } while (0)

    // ---- prologue (t = 0): L1 lanes produce s1(0); L2 lanes have no valid
    // input yet -> reset them before the first broadcast.
    ITER(__ldg(rowA + 0), __ldg(rowB + 0));
    if (isL2) { ccA = 0.f; outA = 0.f; ccB = 0.f; outB = 0.f; }
    BCAST();

    // ---- main loop: t = 1..T-1. L1 computes s1(t); L2 computes h2(t-1).
#pragma unroll 2
    for (int t = 1; t < T; ++t) {
        const float xa = __ldg(rowA + t);
        const float xb = __ldg(rowB + t);
        ITER(xa, xb);
        BCAST();
    }

    // ---- epilogue: one more step so L2 lanes produce h2(T-1).
    // (x unused by L2 lanes since A=0; L1 output is never consumed.)
    ITER(0.0f, 0.0f);

    // gather final h2 (held by lanes gbase+3..5) and apply dense head
    const float FA0 = __shfl_sync(FULLM, outA, gbase + 3);
    const float FA1 = __shfl_sync(FULLM, outA, gbase + 4);
    const float FA2 = __shfl_sync(FULLM, outA, gbase + 5);
    const float FB0 = __shfl_sync(FULLM, outB, gbase + 3);
    const float FB1 = __shfl_sync(FULLM, outB, gbase + 4);
    const float FB2 = __shfl_sync(FULLM, outB, gbase + 5);

    if (role == 0 && actA) {
        const float w0 = __ldg(Wd + 0), w1 = __ldg(Wd + 1), w2 = __ldg(Wd + 2);
        const float b0 = __ldg(bd);
        out[eA] = fmaf(FA2, w2, fmaf(FA1, w1, fmaf(FA0, w0, b0)));
        if (actB)
            out[eB] = fmaf(FB2, w2, fmaf(FB1, w1, fmaf(FB0, w0, b0)));
    }

#undef STEP
#undef ITER
#undef BCAST
}

extern "C" void kernel_launch(void* const* d_in, const int* in_sizes, int n_in,
                              void* d_out, int out_size)
{
    const float* state = (const float*)d_in[0];
    const float* W1 = (const float*)d_in[1];
    const float* U1 = (const float*)d_in[2];
    const float* b1 = (const float*)d_in[3];
    const float* W2 = (const float*)d_in[4];
    const float* U2 = (const float*)d_in[5];
    const float* b2 = (const float*)d_in[6];
    const float* Wd = (const float*)d_in[7];
    const float* bd = (const float*)d_in[8];
    float* out = (float*)d_out;

    const int B = out_size;            // output is [1, B]
    const int T = in_sizes[0] / B;     // state is [B, T]

    const int pairs = (B + 1) / 2;             // elements handled as (eA, eA+pairs)
    const int warps = (pairs + 4) / 5;         // 5 element-pairs per warp
    const int threads = 128;                   // 4 warps -> one per SMSP
    const int blocks = (warps + 3) / 4;
    lstm2_dual_kernel<<<blocks, threads>>>(state, W1, U1, b1, W2, U2, b2, Wd, bd,
                                           out, B, T, pairs);
}

// round 5
// speedup vs baseline: 1.0842x; 1.0842x over previous
#include <cuda_runtime.h>

// LSTMBrain: 2-layer LSTM (hidden=3) over [B=4096, T=2048], dense head 3->1.
// Round 5: R3 layout (8 lanes/element: lanes 0-2 L1 units, 4-6 L2 units,
// 3/7 harmless dups; 4 elements/warp; 1024 warps; 128 blocks x 256 thr =
// 2 warps/SMSP on 128 SMs) BUT the per-step state broadcast goes through
// SHARED MEMORY (STS.32 + syncwarp + 2x broadcast LDS.128, double-buffered)
// instead of 6 shfl.sync — R3/R4 timing fits SHFL rt ~26 cyc/warp, making
// shfl the binding pipe. Also: algebraic MUFU reduction to 8/step:
//   si*tg  = (2-d2) * rcp(d0*d2)        (ig product, one rcp)
//   out    = (2-dc) * rcp(dc*d3)        (o-gate * tanh(c), one rcp)
//   cell kept in the -2log2e-scaled domain (dc = 1 + ex2(cc)).

#define FULLM 0xFFFFFFFFu
#define LOG2E 1.4426950408889634f

__device__ __forceinline__ float fast_rcp(float x) {
    float r; asm("rcp.approx.f32 %0, %1;" : "=f"(r) : "f"(x)); return r;
}
__device__ __forceinline__ float fast_ex2(float x) {
    float r; asm("ex2.approx.f32 %0, %1;" : "=f"(r) : "f"(x)); return r;
}

__global__ void __launch_bounds__(256, 1) lstm2_smem_kernel(
    const float* __restrict__ state,
    const float* __restrict__ W1, const float* __restrict__ U1, const float* __restrict__ b1,
    const float* __restrict__ W2, const float* __restrict__ U2, const float* __restrict__ b2,
    const float* __restrict__ Wd, const float* __restrict__ bd,
    float* __restrict__ out, int B, int T)
{
    // smem exchange: [warp][buffer][lane], 16B-aligned, double-buffered
    __shared__ __align__(16) float xch[8][2][32];

    const int tid   = blockIdx.x * 256 + threadIdx.x;
    const int w     = threadIdx.x >> 5;        // warp in block (0..7)
    const int lane  = threadIdx.x & 31;
    const int lane8 = lane & 7;                // role in 8-lane group
    const int gbase = lane & ~7;               // group's first lane (0,8,16,24)
    const int sub   = lane8 & 3;
    const int u     = (sub < 3) ? sub : 2;     // owned hidden unit (3/7 dup 2)
    const bool isL2 = (lane8 & 4) != 0;
    int b = tid >> 3;                          // batch element of this group
    const bool valid = (b < B);
    if (!valid) b = B - 1;

    // ---- per-lane coefficients, pre-scaled into the ex2 domain ----
    // gate g = 0:i 1:f 2:g(tanh) 3:o ; column = g*3 + u
    // sigma gates scaled by -log2e, tanh gate by -2log2e.
    float A[4], bias[4], Bk[3][4], Ck[3][4];
#pragma unroll
    for (int g = 0; g < 4; ++g) {
        const int col = g * 3 + u;
        const float sc = (g == 2) ? (-2.0f * LOG2E) : (-LOG2E);
        if (isL2) {
            A[g]    = 0.0f;
            bias[g] = __ldg(b2 + col) * sc;
#pragma unroll
            for (int k = 0; k < 3; ++k) {
                Bk[k][g] = __ldg(W2 + k * 12 + col) * sc;   // * s1 broadcast
                Ck[k][g] = __ldg(U2 + k * 12 + col) * sc;   // * h2 broadcast
            }
        } else {
            A[g]    = __ldg(W1 + col) * sc;
            bias[g] = __ldg(b1 + col) * sc;
#pragma unroll
            for (int k = 0; k < 3; ++k) {
                Bk[k][g] = __ldg(U1 + k * 12 + col) * sc;   // * s1 broadcast
                Ck[k][g] = 0.0f;
            }
        }
    }

    const float* xrow = state + (size_t)b * (size_t)T;

    float cc   = 0.0f;   // own-unit cell state, in -2log2e scaled domain
    float outv = 0.0f;   // own-unit hidden output (s1 for L1, h2 for L2 lanes)
    float S0 = 0.f, S1 = 0.f, S2 = 0.f;   // broadcast s1(t-1)
    float H0 = 0.f, H1 = 0.f, H2 = 0.f;   // broadcast h2(t-2)

    // STEP: z-gates, activations (8 MUFU total), cell update, outv.
#define STEP(xv)                                                            \
    do {                                                                    \
        float z0 = fmaf(A[0], (xv), bias[0]);                               \
        float z1 = fmaf(A[1], (xv), bias[1]);                               \
        float z2 = fmaf(A[2], (xv), bias[2]);                               \
        float z3 = fmaf(A[3], (xv), bias[3]);                               \
        z0 = fmaf(Bk[0][0], S0, z0); z1 = fmaf(Bk[0][1], S0, z1);           \
        z2 = fmaf(Bk[0][2], S0, z2); z3 = fmaf(Bk[0][3], S0, z3);           \
        z0 = fmaf(Bk[1][0], S1, z0); z1 = fmaf(Bk[1][1], S1, z1);           \
        z2 = fmaf(Bk[1][2], S1, z2); z3 = fmaf(Bk[1][3], S1, z3);           \
        z0 = fmaf(Bk[2][0], S2, z0); z1 = fmaf(Bk[2][1], S2, z1);           \
        z2 = fmaf(Bk[2][2], S2, z2); z3 = fmaf(Bk[2][3], S2, z3);           \
        z0 = fmaf(Ck[0][0], H0, z0); z1 = fmaf(Ck[0][1], H0, z1);           \
        z2 = fmaf(Ck[0][2], H0, z2); z3 = fmaf(Ck[0][3], H0, z3);           \
        z0 = fmaf(Ck[1][0], H1, z0); z1 = fmaf(Ck[1][1], H1, z1);           \
        z2 = fmaf(Ck[1][2], H1, z2); z3 = fmaf(Ck[1][3], H1, z3);           \
        z0 = fmaf(Ck[2][0], H2, z0); z1 = fmaf(Ck[2][1], H2, z1);           \
        z2 = fmaf(Ck[2][2], H2, z2); z3 = fmaf(Ck[2][3], H2, z3);           \
        const float d0 = 1.0f + fast_ex2(z0);                               \
        const float d1 = 1.0f + fast_ex2(z1);                               \
        const float d2 = 1.0f + fast_ex2(z2);                               \
        const float d3 = 1.0f + fast_ex2(z3);                               \
        const float r02 = fast_rcp(d0 * d2);                                \
        const float sf  = fast_rcp(d1);                                     \
        /* p = -2log2e * tanh-gate * sigmoid-i numerator: 2log2e*(d2-2) */  \
        const float p   = fmaf(2.0f * LOG2E, d2, -4.0f * LOG2E);            \
        cc = fmaf(sf, cc, p * r02);                                         \
        const float dc  = 1.0f + fast_ex2(cc);                              \
        const float rc3 = fast_rcp(dc * d3);                                \
        outv = (2.0f - dc) * rc3;                                           \
    } while (0)

    // smem exchange: write own outv, sync, read group's s1/h2 vectors.
#define XCHG(tog)                                                           \
    do {                                                                    \
        xch[w][(tog)][lane] = outv;                                         \
        __syncwarp(FULLM);                                                  \
        const float4 sv = *reinterpret_cast<const float4*>(                 \
            &xch[w][(tog)][gbase]);                                         \
        const float4 hv = *reinterpret_cast<const float4*>(                 \
            &xch[w][(tog)][gbase + 4]);                                     \
        S0 = sv.x; S1 = sv.y; S2 = sv.z;                                    \
        H0 = hv.x; H1 = hv.y; H2 = hv.z;                                    \
    } while (0)

    // ---- prologue (t = 0): L1 produces s1(0); L2 lanes have no valid input
    STEP(__ldg(xrow + 0));
    if (isL2) { cc = 0.0f; outv = 0.0f; }
    XCHG(0);

    // ---- main loop: t = 1..T-1. L1 computes s1(t); L2 computes h2(t-1).
#pragma unroll 2
    for (int t = 1; t < T; ++t) {
        STEP(__ldg(xrow + t));
        XCHG(t & 1);
    }

    // ---- epilogue: one more step so L2 lanes produce h2(T-1). x unused by
    // L2 (A=0); L1 output never consumed.
    STEP(0.0f);
    xch[w][0][lane] = outv;
    __syncwarp(FULLM);

    if (lane8 == 0 && valid) {
        const float F0 = xch[w][0][gbase + 4];
        const float F1 = xch[w][0][gbase + 5];
        const float F2 = xch[w][0][gbase + 6];
        float r = __ldg(bd);
        r = fmaf(F0, __ldg(Wd + 0), r);
        r = fmaf(F1, __ldg(Wd + 1), r);
        r = fmaf(F2, __ldg(Wd + 2), r);
        out[b] = r;
    }

#undef STEP
#undef XCHG
}

extern "C" void kernel_launch(void* const* d_in, const int* in_sizes, int n_in,
                              void* d_out, int out_size)
{
    const float* state = (const float*)d_in[0];
    const float* W1 = (const float*)d_in[1];
    const float* U1 = (const float*)d_in[2];
    const float* b1 = (const float*)d_in[3];
    const float* W2 = (const float*)d_in[4];
    const float* U2 = (const float*)d_in[5];
    const float* b2 = (const float*)d_in[6];
    const float* Wd = (const float*)d_in[7];
    const float* bd = (const float*)d_in[8];
    float* out = (float*)d_out;

    const int B = out_size;            // output is [1, B]
    const int T = in_sizes[0] / B;     // state is [B, T]

    const long long total_threads = (long long)B * 8;   // 8 lanes per element
    const int threads = 256;                            // 8 warps = 2 per SMSP
    const int blocks = (int)((total_threads + threads - 1) / threads);
    lstm2_smem_kernel<<<blocks, threads>>>(state, W1, U1, b1, W2, U2, b2, Wd, bd,
                                           out, B, T);
}

// round 6
// speedup vs baseline: 1.0932x; 1.0083x over previous
#include <cuda_runtime.h>

// LSTMBrain: 2-layer LSTM (hidden=3) over [B=4096, T=2048], dense head 3->1.
// Round 6: per-SMSP issue-throughput model fits R2-R5. Design:
//  - 8-lane groups (lanes 0-2: L1 units, 4-6: L2 units, 3/7 dup), each lane
//    carries TWO elements (eA, eB = eA + B/2) -> 512 warps in 128 blocks of
//    128 threads = EXACTLY 1 warp per SMSP on 128 SMs (W=1 minimizes wall).
//  - All gate-matvec + cell FMA work packed as fma.rn.f32x2 (Blackwell FFMA2,
//    2 FMAs/issue slot): 28 FFMA2 instead of 56 FFMA per timestep.
//  - MUFU merged: per element 5 ex2 + shared rcp(d0*d1*d2) and rcp(dc*d3);
//    the two rcps merged ACROSS elements -> 12 MUFU per iteration.
//  - Exchange via smem: STS.64 of packed (outA,outB), syncwarp, LDS.128 pairs.
// Math identical to R5 (ex2-domain gates), so rel_err stays ~2.6e-5.

typedef unsigned long long u64;

#define FULLM 0xFFFFFFFFu
#define LOG2E 1.4426950408889634f

__device__ __forceinline__ float fast_rcp(float x) {
    float r; asm("rcp.approx.f32 %0, %1;" : "=f"(r) : "f"(x)); return r;
}
__device__ __forceinline__ float fast_ex2(float x) {
    float r; asm("ex2.approx.f32 %0, %1;" : "=f"(r) : "f"(x)); return r;
}
__device__ __forceinline__ u64 ffma2(u64 a, u64 b, u64 c) {
    u64 d; asm("fma.rn.f32x2 %0, %1, %2, %3;" : "=l"(d) : "l"(a), "l"(b), "l"(c));
    return d;
}
__device__ __forceinline__ u64 pack2(float lo, float hi) {
    u64 d; asm("mov.b64 %0, {%1, %2};" : "=l"(d) : "f"(lo), "f"(hi)); return d;
}
__device__ __forceinline__ void unpack2(u64 v, float& lo, float& hi) {
    asm("mov.b64 {%0, %1}, %2;" : "=f"(lo), "=f"(hi) : "l"(v));
}

__global__ void __launch_bounds__(128, 1) lstm2_f32x2_kernel(
    const float* __restrict__ state,
    const float* __restrict__ W1, const float* __restrict__ U1, const float* __restrict__ b1,
    const float* __restrict__ W2, const float* __restrict__ U2, const float* __restrict__ b2,
    const float* __restrict__ Wd, const float* __restrict__ bd,
    float* __restrict__ out, int B, int T, int pairs)
{
    // exchange: [warp][buffer][lane] packed (outA, outB); double-buffered
    __shared__ __align__(16) u64 xch[4][2][32];

    const int tid   = blockIdx.x * 128 + threadIdx.x;
    const int w     = threadIdx.x >> 5;
    const int lane  = threadIdx.x & 31;
    const int lane8 = lane & 7;             // role in 8-lane group
    const int gbase = lane & ~7;            // group's first lane
    const int sub   = lane8 & 3;
    const int u     = (sub < 3) ? sub : 2;  // owned hidden unit (3/7 dup 2)
    const bool isL2 = (lane8 & 4) != 0;

    int g = tid >> 3;                       // group id == element A index
    const bool actA = (g < pairs);
    if (!actA) g = pairs - 1;
    const int eA = g;
    const int eB = g + pairs;
    const bool actB = actA && (eB < B);
    const int eBc = actB ? eB : eA;

    // ---- coefficients, pre-scaled into ex2 domain, packed (same both halves)
    // gate gt = 0:i 1:f 2:g(tanh) 3:o ; weight column = gt*3 + u
    u64 Ap[4], BIp[4], Bp[3][4], Cp[3][4];
#pragma unroll
    for (int gt = 0; gt < 4; ++gt) {
        const int col = gt * 3 + u;
        const float sc = (gt == 2) ? (-2.0f * LOG2E) : (-LOG2E);
        float a, bi, bk[3], ck[3];
        if (isL2) {
            a  = 0.0f;
            bi = __ldg(b2 + col) * sc;
#pragma unroll
            for (int k = 0; k < 3; ++k) {
                bk[k] = __ldg(W2 + k * 12 + col) * sc;   // * s1 broadcast
                ck[k] = __ldg(U2 + k * 12 + col) * sc;   // * h2 broadcast
            }
        } else {
            a  = __ldg(W1 + col) * sc;
            bi = __ldg(b1 + col) * sc;
#pragma unroll
            for (int k = 0; k < 3; ++k) {
                bk[k] = __ldg(U1 + k * 12 + col) * sc;   // * s1 broadcast
                ck[k] = 0.0f;
            }
        }
        Ap[gt]  = pack2(a, a);
        BIp[gt] = pack2(bi, bi);
#pragma unroll
        for (int k = 0; k < 3; ++k) {
            Bp[k][gt] = pack2(bk[k], bk[k]);
            Cp[k][gt] = pack2(ck[k], ck[k]);
        }
    }

    const float* rowA = state + (size_t)eA  * (size_t)T;
    const float* rowB = state + (size_t)eBc * (size_t)T;

    float ccA = 0.f, ccB = 0.f;            // scaled cell states (own unit)
    float outA = 0.f, outB = 0.f;          // own-unit hidden outputs
    u64 S0 = 0, S1 = 0, S2 = 0;            // packed s1(t-1) broadcasts (A,B)
    u64 H0 = 0, H1 = 0, H2 = 0;            // packed h2(t-2) broadcasts (A,B)

    // STEP: both elements' gate math for one timestep. 28 FFMA2 + 12 MUFU.
#define STEP(xa, xb)                                                        \
    do {                                                                    \
        const u64 xab = pack2((xa), (xb));                                  \
        u64 z0 = ffma2(Ap[0], xab, BIp[0]);                                 \
        u64 z1 = ffma2(Ap[1], xab, BIp[1]);                                 \
        u64 z2 = ffma2(Ap[2], xab, BIp[2]);                                 \
        u64 z3 = ffma2(Ap[3], xab, BIp[3]);                                 \
        z0 = ffma2(Bp[0][0], S0, z0); z1 = ffma2(Bp[0][1], S0, z1);         \
        z2 = ffma2(Bp[0][2], S0, z2); z3 = ffma2(Bp[0][3], S0, z3);         \
        z0 = ffma2(Bp[1][0], S1, z0); z1 = ffma2(Bp[1][1], S1, z1);         \
        z2 = ffma2(Bp[1][2], S1, z2); z3 = ffma2(Bp[1][3], S1, z3);         \
        z0 = ffma2(Bp[2][0], S2, z0); z1 = ffma2(Bp[2][1], S2, z1);         \
        z2 = ffma2(Bp[2][2], S2, z2); z3 = ffma2(Bp[2][3], S2, z3);         \
        z0 = ffma2(Cp[0][0], H0, z0); z1 = ffma2(Cp[0][1], H0, z1);         \
        z2 = ffma2(Cp[0][2], H0, z2); z3 = ffma2(Cp[0][3], H0, z3);         \
        z0 = ffma2(Cp[1][0], H1, z0); z1 = ffma2(Cp[1][1], H1, z1);         \
        z2 = ffma2(Cp[1][2], H1, z2); z3 = ffma2(Cp[1][3], H1, z3);         \
        z0 = ffma2(Cp[2][0], H2, z0); z1 = ffma2(Cp[2][1], H2, z1);         \
        z2 = ffma2(Cp[2][2], H2, z2); z3 = ffma2(Cp[2][3], H2, z3);         \
        float zA0, zB0, zA1, zB1, zA2, zB2, zA3, zB3;                       \
        unpack2(z0, zA0, zB0); unpack2(z1, zA1, zB1);                       \
        unpack2(z2, zA2, zB2); unpack2(z3, zA3, zB3);                       \
        const float dA0 = 1.0f + fast_ex2(zA0);                             \
        const float dA1 = 1.0f + fast_ex2(zA1);                             \
        const float dA2 = 1.0f + fast_ex2(zA2);                             \
        const float dA3 = 1.0f + fast_ex2(zA3);                             \
        const float dB0 = 1.0f + fast_ex2(zB0);                             \
        const float dB1 = 1.0f + fast_ex2(zB1);                             \
        const float dB2 = 1.0f + fast_ex2(zB2);                             \
        const float dB3 = 1.0f + fast_ex2(zB3);                             \
        const float mA = dA0 * dA2, mB = dB0 * dB2;                         \
        const float PA = mA * dA1,  PB = mB * dB1;                          \
        const float r6 = fast_rcp(PA * PB);                                 \
        const float rA = r6 * PB,   rB = r6 * PA;   /* 1/PA, 1/PB */        \
        const float sfA = rA * mA,  sfB = rB * mB;  /* 1/d1 */              \
        const float r02A = rA * dA1, r02B = rB * dB1; /* 1/(d0*d2) */       \
        const float pA = fmaf(2.0f * LOG2E, dA2, -4.0f * LOG2E);            \
        const float pB = fmaf(2.0f * LOG2E, dB2, -4.0f * LOG2E);            \
        ccA = fmaf(sfA, ccA, pA * r02A);                                    \
        ccB = fmaf(sfB, ccB, pB * r02B);                                    \
        const float dcA = 1.0f + fast_ex2(ccA);                             \
        const float dcB = 1.0f + fast_ex2(ccB);                             \
        const float qA = dcA * dA3, qB = dcB * dB3;                         \
        const float rq = fast_rcp(qA * qB);                                 \
        outA = (2.0f - dcA) * (rq * qB);                                    \
        outB = (2.0f - dcB) * (rq * qA);                                    \
    } while (0)

#define XCHG(tog)                                                           \
    do {                                                                    \
        xch[w][(tog)][lane] = pack2(outA, outB);                            \
        __syncwarp(FULLM);                                                  \
        const ulonglong2 v0 =                                               \
            *reinterpret_cast<const ulonglong2*>(&xch[w][(tog)][gbase]);    \
        const ulonglong2 v1 =                                               \
            *reinterpret_cast<const ulonglong2*>(&xch[w][(tog)][gbase + 2]);\
        const ulonglong2 v2 =                                               \
            *reinterpret_cast<const ulonglong2*>(&xch[w][(tog)][gbase + 4]);\
        const ulonglong2 v3 =                                               \
            *reinterpret_cast<const ulonglong2*>(&xch[w][(tog)][gbase + 6]);\
        S0 = v0.x; S1 = v0.y; S2 = v1.x;                                    \
        H0 = v2.x; H1 = v2.y; H2 = v3.x;                                    \
    } while (0)

    // ---- prologue (t = 0): L1 produces s1(0); L2 lanes have no valid input
    STEP(__ldg(rowA + 0), __ldg(rowB + 0));
    if (isL2) { ccA = 0.f; ccB = 0.f; outA = 0.f; outB = 0.f; }
    XCHG(0);

    // ---- main loop: t = 1..T-1. L1 computes s1(t); L2 computes h2(t-1).
    int t = 1;
    for (; t + 4 <= T; t += 4) {
        const float4 xa4 = __ldg(reinterpret_cast<const float4*>(rowA + t - 1) + 0);
        const float4 xb4 = __ldg(reinterpret_cast<const float4*>(rowB + t - 1) + 0);
        // note: t-1 is 4-aligned only when t%4==1 and T%4==0; t starts at 1
        // and steps by 4, rows are T=2048 floats -> (t-1) multiple of 4. OK.
        STEP(xa4.y, xb4.y); XCHG(1);
        STEP(xa4.z, xb4.z); XCHG(0);
        STEP(xa4.w, xb4.w); XCHG(1);
        const float xa = __ldg(rowA + t + 3);
        const float xb = __ldg(rowB + t + 3);
        STEP(xa, xb);       XCHG(0);
    }
    for (; t < T; ++t) {
        STEP(__ldg(rowA + t), __ldg(rowB + t));
        XCHG(t & 1);
    }

    // ---- epilogue: one more step so L2 lanes produce h2(T-1). x unused by
    // L2 (A = 0); L1 lanes' output is never consumed.
    STEP(0.0f, 0.0f);
    xch[w][0][lane] = pack2(outA, outB);
    __syncwarp(FULLM);

    if (lane8 == 0 && actA) {
        float f0A, f0B, f1A, f1B, f2A, f2B;
        unpack2(xch[w][0][gbase + 4], f0A, f0B);
        unpack2(xch[w][0][gbase + 5], f1A, f1B);
        unpack2(xch[w][0][gbase + 6], f2A, f2B);
        const float w0 = __ldg(Wd + 0), w1 = __ldg(Wd + 1), w2 = __ldg(Wd + 2);
        const float b0 = __ldg(bd);
        out[eA] = fmaf(f2A, w2, fmaf(f1A, w1, fmaf(f0A, w0, b0)));
        if (actB)
            out[eB] = fmaf(f2B, w2, fmaf(f1B, w1, fmaf(f0B, w0, b0)));
    }

#undef STEP
#undef XCHG
}

extern "C" void kernel_launch(void* const* d_in, const int* in_sizes, int n_in,
                              void* d_out, int out_size)
{
    const float* state = (const float*)d_in[0];
    const float* W1 = (const float*)d_in[1];
    const float* U1 = (const float*)d_in[2];
    const float* b1 = (const float*)d_in[3];
    const float* W2 = (const float*)d_in[4];
    const float* U2 = (const float*)d_in[5];
    const float* b2 = (const float*)d_in[6];
    const float* Wd = (const float*)d_in[7];
    const float* bd = (const float*)d_in[8];
    float* out = (float*)d_out;

    const int B = out_size;            // output is [1, B]
    const int T = in_sizes[0] / B;     // state is [B, T]

    const int pairs = (B + 1) / 2;                    // (eA, eA + pairs)
    const long long total_threads = (long long)pairs * 8;
    const int threads = 128;                          // 4 warps -> 1 per SMSP
    const int blocks = (int)((total_threads + threads - 1) / threads);
    lstm2_f32x2_kernel<<<blocks, threads>>>(state, W1, U1, b1, W2, U2, b2,
                                            Wd, bd, out, B, T, pairs);
}

// round 7
// speedup vs baseline: 1.1521x; 1.0539x over previous
#include <cuda_runtime.h>

// LSTMBrain: 2-layer LSTM (hidden=3) over [B=4096, T=2048], dense head 3->1.
// Round 7: model wall/step = C_chain + MUFU_queue(SMSP). Design:
//  - 8-lane groups (0-2: L1 units, 4-6: L2 units, 3/7 dup), dual elements
//    per lane (eA, eB=eA+B/2) packed in fma.rn.f32x2 -> 512 warps.
//  - 32-thread blocks, 512 CTAs over 148 SMs -> <= 1 warp per SMSP
//    (minimizes MUFU queuing added to the recurrence chain).
//  - z-matvec TREE'd (depth 3 from broadcast arrival, was 7-deep serial).
//  - A/B chains kept independent; the three rcps paired ACROSS elements
//    only where both operands are ready in parallel (chain-neutral):
//    13 MUFU per warp-step (10 ex2 + 3 rcp) -> 104 cyc MUFU pipe.
//  - smem exchange: STS.64 + syncwarp + 4x LDS.128, double-buffered.
//  - x prefetched one float4-chunk ahead (LDG off the chain).

typedef unsigned long long u64;

#define FULLM 0xFFFFFFFFu
#define LOG2E 1.4426950408889634f

__device__ __forceinline__ float fast_rcp(float x) {
    float r; asm("rcp.approx.f32 %0, %1;" : "=f"(r) : "f"(x)); return r;
}
__device__ __forceinline__ float fast_ex2(float x) {
    float r; asm("ex2.approx.f32 %0, %1;" : "=f"(r) : "f"(x)); return r;
}
__device__ __forceinline__ u64 ffma2(u64 a, u64 b, u64 c) {
    u64 d; asm("fma.rn.f32x2 %0, %1, %2, %3;" : "=l"(d) : "l"(a), "l"(b), "l"(c));
    return d;
}
__device__ __forceinline__ u64 fmul2(u64 a, u64 b) {
    u64 d; asm("mul.rn.f32x2 %0, %1, %2;" : "=l"(d) : "l"(a), "l"(b)); return d;
}
__device__ __forceinline__ u64 fadd2(u64 a, u64 b) {
    u64 d; asm("add.rn.f32x2 %0, %1, %2;" : "=l"(d) : "l"(a), "l"(b)); return d;
}
__device__ __forceinline__ u64 pack2(float lo, float hi) {
    u64 d; asm("mov.b64 %0, {%1, %2};" : "=l"(d) : "f"(lo), "f"(hi)); return d;
}
__device__ __forceinline__ void unpack2(u64 v, float& lo, float& hi) {
    asm("mov.b64 {%0, %1}, %2;" : "=f"(lo), "=f"(hi) : "l"(v));
}

__global__ void __launch_bounds__(32, 1) lstm2_r7_kernel(
    const float* __restrict__ state,
    const float* __restrict__ W1, const float* __restrict__ U1, const float* __restrict__ b1,
    const float* __restrict__ W2, const float* __restrict__ U2, const float* __restrict__ b2,
    const float* __restrict__ Wd, const float* __restrict__ bd,
    float* __restrict__ out, int B, int T, int pairs)
{
    __shared__ __align__(16) u64 xch[2][32];   // [buffer][lane], packed (A,B)

    const int lane  = threadIdx.x & 31;
    const int lane8 = lane & 7;
    const int gbase = lane & ~7;
    const int sub   = lane8 & 3;
    const int u     = (sub < 3) ? sub : 2;     // owned hidden unit (3/7 dup 2)
    const bool isL2 = (lane8 & 4) != 0;

    int g = blockIdx.x * 4 + (lane >> 3);      // group id == element A index
    const bool actA = (g < pairs);
    if (!actA) g = pairs - 1;
    const int eA = g;
    const int eB = g + pairs;
    const bool actB = actA && (eB < B);
    const int eBc = actB ? eB : eA;

    // ---- coefficients, pre-scaled into the ex2 domain, packed both halves
    // gate gt = 0:i 1:f 2:g(tanh) 3:o ; weight column = gt*3 + u
    u64 Ap[4], BIp[4], Bp[3][4], Cp[3][4];
#pragma unroll
    for (int gt = 0; gt < 4; ++gt) {
        const int col = gt * 3 + u;
        const float sc = (gt == 2) ? (-2.0f * LOG2E) : (-LOG2E);
        float a, bi, bk[3], ck[3];
        if (isL2) {
            a  = 0.0f;
            bi = __ldg(b2 + col) * sc;
#pragma unroll
            for (int k = 0; k < 3; ++k) {
                bk[k] = __ldg(W2 + k * 12 + col) * sc;   // * s1 broadcast
                ck[k] = __ldg(U2 + k * 12 + col) * sc;   // * h2 broadcast
            }
        } else {
            a  = __ldg(W1 + col) * sc;
            bi = __ldg(b1 + col) * sc;
#pragma unroll
            for (int k = 0; k < 3; ++k) {
                bk[k] = __ldg(U1 + k * 12 + col) * sc;   // * s1 broadcast
                ck[k] = 0.0f;
            }
        }
        Ap[gt]  = pack2(a, a);
        BIp[gt] = pack2(bi, bi);
#pragma unroll
        for (int k = 0; k < 3; ++k) {
            Bp[k][gt] = pack2(bk[k], bk[k]);
            Cp[k][gt] = pack2(ck[k], ck[k]);
        }
    }

    const float* rowA = state + (size_t)eA  * (size_t)T;
    const float* rowB = state + (size_t)eBc * (size_t)T;

    float ccA = 0.f, ccB = 0.f;           // scaled cell states (own unit)
    float outA = 0.f, outB = 0.f;         // own-unit hidden outputs
    u64 S0 = 0, S1 = 0, S2 = 0;           // packed s1(t-1) broadcasts
    u64 H0 = 0, H1 = 0, H2 = 0;           // packed h2(t-2) broadcasts

    // STEP: one timestep for both elements. z tree'd (depth 3 from S/H);
    // activations: 10 ex2 + 3 paired rcp (chain-neutral pairing).
#define STEP(xa, xb)                                                        \
    do {                                                                    \
        const u64 xab = pack2((xa), (xb));                                  \
        float zA0, zB0, zA1, zB1, zA2, zB2, zA3, zB3;                       \
        {                                                                   \
            u64 z[4];                                                       \
            _Pragma("unroll")                                               \
            for (int gt = 0; gt < 4; ++gt) {                                \
                const u64 uu = ffma2(Bp[0][gt], S0,                         \
                                 ffma2(Bp[1][gt], S1,                       \
                                   ffma2(Ap[gt], xab, BIp[gt])));           \
                const u64 vv = ffma2(Cp[0][gt], H0,                         \
                                 ffma2(Cp[1][gt], H1,                       \
                                   ffma2(Cp[2][gt], H2,                     \
                                     fmul2(Bp[2][gt], S2))));               \
                z[gt] = fadd2(uu, vv);                                      \
            }                                                               \
            unpack2(z[0], zA0, zB0); unpack2(z[1], zA1, zB1);               \
            unpack2(z[2], zA2, zB2); unpack2(z[3], zA3, zB3);               \
        }                                                                   \
        const float dA0 = 1.0f + fast_ex2(zA0);                             \
        const float dA1 = 1.0f + fast_ex2(zA1);                             \
        const float dA2 = 1.0f + fast_ex2(zA2);                             \
        const float dA3 = 1.0f + fast_ex2(zA3);                             \
        const float dB0 = 1.0f + fast_ex2(zB0);                             \
        const float dB1 = 1.0f + fast_ex2(zB1);                             \
        const float dB2 = 1.0f + fast_ex2(zB2);                             \
        const float dB3 = 1.0f + fast_ex2(zB3);                             \
        /* paired rcp #1: 1/(d0*d2) for both elements (operands parallel) */\
        const float mA = dA0 * dA2, mB = dB0 * dB2;                         \
        const float Rm = fast_rcp(mA * mB);                                 \
        const float r02A = Rm * mB, r02B = Rm * mA;                         \
        /* paired rcp #2: 1/d1 (forget gates) */                            \
        const float Rf  = fast_rcp(dA1 * dB1);                              \
        const float sfA = Rf * dB1, sfB = Rf * dA1;                         \
        const float pA = fmaf(2.0f * LOG2E, dA2, -4.0f * LOG2E);            \
        const float pB = fmaf(2.0f * LOG2E, dB2, -4.0f * LOG2E);            \
        ccA = fmaf(sfA, ccA, pA * r02A);                                    \
        ccB = fmaf(sfB, ccB, pB * r02B);                                    \
        const float dcA = 1.0f + fast_ex2(ccA);                             \
        const float dcB = 1.0f + fast_ex2(ccB);                             \
        /* paired rcp #3: 1/(dc*d3) (operands parallel across elements) */  \
        const float qA = dcA * dA3, qB = dcB * dB3;                         \
        const float Rq = fast_rcp(qA * qB);                                 \
        outA = (2.0f - dcA) * (Rq * qB);                                    \
        outB = (2.0f - dcB) * (Rq * qA);                                    \
    } while (0)

#define XCHG(p)                                                             \
    do {                                                                    \
        xch[(p)][lane] = pack2(outA, outB);                                 \
        __syncwarp(FULLM);                                                  \
        const ulonglong2 v0 =                                               \
            *reinterpret_cast<const ulonglong2*>(&xch[(p)][gbase]);         \
        const ulonglong2 v1 =                                               \
            *reinterpret_cast<const ulonglong2*>(&xch[(p)][gbase + 2]);     \
        const ulonglong2 v2 =                                               \
            *reinterpret_cast<const ulonglong2*>(&xch[(p)][gbase + 4]);     \
        const ulonglong2 v3 =                                               \
            *reinterpret_cast<const ulonglong2*>(&xch[(p)][gbase + 6]);     \
        S0 = v0.x; S1 = v0.y; S2 = v1.x;                                    \
        H0 = v2.x; H1 = v2.y; H2 = v3.x;                                    \
    } while (0)

#define BODY(xa, xb, p) do { STEP((xa), (xb)); XCHG(p); } while (0)

    // ---- prologue: t = 0..3 with one-chunk-ahead prefetch (T >= 8, T%4==0
    // for the fast path; scalar tail below covers any remainder).
    float4 a4 = __ldg(reinterpret_cast<const float4*>(rowA));
    float4 b4 = __ldg(reinterpret_cast<const float4*>(rowB));
    float4 nA, nB;
    if (T >= 8) {
        nA = __ldg(reinterpret_cast<const float4*>(rowA + 4));
        nB = __ldg(reinterpret_cast<const float4*>(rowB + 4));
    }

    STEP(a4.x, b4.x);                      // t = 0: L1 valid, L2 garbage
    if (isL2) { ccA = 0.f; ccB = 0.f; outA = 0.f; outB = 0.f; }
    XCHG(0);
    BODY(a4.y, b4.y, 1);                   // t = 1
    BODY(a4.z, b4.z, 0);                   // t = 2
    BODY(a4.w, b4.w, 1);                   // t = 3

    int t = 4;
    for (; t + 7 < T; t += 4) {
        a4 = nA; b4 = nB;
        nA = __ldg(reinterpret_cast<const float4*>(rowA + t + 4));
        nB = __ldg(reinterpret_cast<const float4*>(rowB + t + 4));
        BODY(a4.x, b4.x, 0);
        BODY(a4.y, b4.y, 1);
        BODY(a4.z, b4.z, 0);
        BODY(a4.w, b4.w, 1);
    }
    if (t + 3 < T) {                       // final full chunk (prefetched)
        a4 = nA; b4 = nB;
        BODY(a4.x, b4.x, 0);
        BODY(a4.y, b4.y, 1);
        BODY(a4.z, b4.z, 0);
        BODY(a4.w, b4.w, 1);
        t += 4;
    }
    for (; t < T; ++t) {                   // scalar tail (not taken for T=2048)
        const float xa = __ldg(rowA + t);
        const float xb = __ldg(rowB + t);
        STEP(xa, xb);
        XCHG(t & 1);
    }

    // ---- epilogue: one more step so L2 lanes produce h2(T-1). x unused by
    // L2 (A = 0); L1 lanes' output is never consumed.
    STEP(0.0f, 0.0f);
    xch[0][lane] = pack2(outA, outB);
    __syncwarp(FULLM);

    if (lane8 == 0 && actA) {
        float f0A, f0B, f1A, f1B, f2A, f2B;
        unpack2(xch[0][gbase + 4], f0A, f0B);
        unpack2(xch[0][gbase + 5], f1A, f1B);
        unpack2(xch[0][gbase + 6], f2A, f2B);
        const float w0 = __ldg(Wd + 0), w1 = __ldg(Wd + 1), w2 = __ldg(Wd + 2);
        const float b0 = __ldg(bd);
        out[eA] = fmaf(f2A, w2, fmaf(f1A, w1, fmaf(f0A, w0, b0)));
        if (actB)
            out[eB] = fmaf(f2B, w2, fmaf(f1B, w1, fmaf(f0B, w0, b0)));
    }

#undef STEP
#undef XCHG
#undef BODY
}

extern "C" void kernel_launch(void* const* d_in, const int* in_sizes, int n_in,
                              void* d_out, int out_size)
{
    const float* state = (const float*)d_in[0];
    const float* W1 = (const float*)d_in[1];
    const float* U1 = (const float*)d_in[2];
    const float* b1 = (const float*)d_in[3];
    const float* W2 = (const float*)d_in[4];
    const float* U2 = (const float*)d_in[5];
    const float* b2 = (const float*)d_in[6];
    const float* Wd = (const float*)d_in[7];
    const float* bd = (const float*)d_in[8];
    float* out = (float*)d_out;

    const int B = out_size;            // output is [1, B]
    const int T = in_sizes[0] / B;     // state is [B, T]

    const int pairs = (B + 1) / 2;     // element pair (eA, eA + pairs)
    const int groups_per_warp = 4;     // 4 groups x 8 lanes = 32
    const int blocks = (pairs + groups_per_warp - 1) / groups_per_warp;
    lstm2_r7_kernel<<<blocks, 32>>>(state, W1, U1, b1, W2, U2, b2,
                                    Wd, bd, out, B, T, pairs);
}

// round 8
// speedup vs baseline: 1.1700x; 1.0155x over previous
#include <cuda_runtime.h>

// LSTMBrain: 2-layer LSTM (hidden=3) over [B=4096, T=2048], dense head 3->1.
// Round 8: additive per-warp pipe-cost model (fits R2-R7). Keep R6 skeleton
// (8-lane groups: 0-2 L1 units, 4-6 L2 units, 3/7 dup; dual elements per lane
// packed f32x2; 512 warps in 512x32 -> 1 warp/SMSP). Cut the fat:
//  - glue packed f32x2 across the (A,B) element pair: ~44 FMA-cyc (was ~90);
//    cc state carried packed (u64).
//  - exchange: permuted slots -> STS.64 + syncwarp + 3x LDS.128.
//  - serial 7-term z (28 ffma2, minimum instruction count).
// MUFU stays 13/step (10 ex2 + 3 paired rcp) — the algebra floor.

typedef unsigned long long u64;

#define FULLM 0xFFFFFFFFu
#define LOG2E 1.4426950408889634f

__device__ __forceinline__ float fast_rcp(float x) {
    float r; asm("rcp.approx.f32 %0, %1;" : "=f"(r) : "f"(x)); return r;
}
__device__ __forceinline__ float fast_ex2(float x) {
    float r; asm("ex2.approx.f32 %0, %1;" : "=f"(r) : "f"(x)); return r;
}
__device__ __forceinline__ u64 ffma2(u64 a, u64 b, u64 c) {
    u64 d; asm("fma.rn.f32x2 %0, %1, %2, %3;" : "=l"(d) : "l"(a), "l"(b), "l"(c));
    return d;
}
__device__ __forceinline__ u64 fmul2(u64 a, u64 b) {
    u64 d; asm("mul.rn.f32x2 %0, %1, %2;" : "=l"(d) : "l"(a), "l"(b)); return d;
}
__device__ __forceinline__ u64 fadd2(u64 a, u64 b) {
    u64 d; asm("add.rn.f32x2 %0, %1, %2;" : "=l"(d) : "l"(a), "l"(b)); return d;
}
__device__ __forceinline__ u64 pack2(float lo, float hi) {
    u64 d; asm("mov.b64 %0, {%1, %2};" : "=l"(d) : "f"(lo), "f"(hi)); return d;
}
__device__ __forceinline__ void unpack2(u64 v, float& lo, float& hi) {
    asm("mov.b64 {%0, %1}, %2;" : "=f"(lo), "=f"(hi) : "l"(v));
}

__global__ void __launch_bounds__(32, 1) lstm2_r8_kernel(
    const float* __restrict__ state,
    const float* __restrict__ W1, const float* __restrict__ U1, const float* __restrict__ b1,
    const float* __restrict__ W2, const float* __restrict__ U2, const float* __restrict__ b2,
    const float* __restrict__ Wd, const float* __restrict__ bd,
    float* __restrict__ out, int B, int T, int pairs)
{
    __shared__ __align__(16) u64 xch[2][32];   // [buffer][slot], packed (A,B)

    const int lane  = threadIdx.x & 31;
    const int lane8 = lane & 7;
    const int gbase = lane & ~7;
    const int sub   = lane8 & 3;
    const int u     = (sub < 3) ? sub : 2;     // owned hidden unit (3/7 dup 2)
    const bool isL2 = (lane8 & 4) != 0;
    // permuted write slot: roles 0,1,2 -> 0,1,2 ; 4,5,6 -> 3,4,5 ; dups -> 6,7
    const int sslot = gbase + ((lane8 < 3) ? lane8
                        : (lane8 == 3) ? 6
                        : (lane8 < 7) ? (lane8 - 1) : 7);

    int g = blockIdx.x * 4 + (lane >> 3);      // group id == element A index
    const bool actA = (g < pairs);
    if (!actA) g = pairs - 1;
    const int eA = g;
    const int eB = g + pairs;
    const bool actB = actA && (eB < B);
    const int eBc = actB ? eB : eA;

    // ---- coefficients, pre-scaled into the ex2 domain, packed both halves
    // gate gt = 0:i 1:f 2:g(tanh) 3:o ; weight column = gt*3 + u
    u64 Ap[4], BIp[4], Bp[3][4], Cp[3][4];
#pragma unroll
    for (int gt = 0; gt < 4; ++gt) {
        const int col = gt * 3 + u;
        const float sc = (gt == 2) ? (-2.0f * LOG2E) : (-LOG2E);
        float a, bi, bk[3], ck[3];
        if (isL2) {
            a  = 0.0f;
            bi = __ldg(b2 + col) * sc;
#pragma unroll
            for (int k = 0; k < 3; ++k) {
                bk[k] = __ldg(W2 + k * 12 + col) * sc;   // * s1 broadcast
                ck[k] = __ldg(U2 + k * 12 + col) * sc;   // * h2 broadcast
            }
        } else {
            a  = __ldg(W1 + col) * sc;
            bi = __ldg(b1 + col) * sc;
#pragma unroll
            for (int k = 0; k < 3; ++k) {
                bk[k] = __ldg(U1 + k * 12 + col) * sc;   // * s1 broadcast
                ck[k] = 0.0f;
            }
        }
        Ap[gt]  = pack2(a, a);
        BIp[gt] = pack2(bi, bi);
#pragma unroll
        for (int k = 0; k < 3; ++k) {
            Bp[k][gt] = pack2(bk[k], bk[k]);
            Cp[k][gt] = pack2(ck[k], ck[k]);
        }
    }

    const u64 ONE2  = pack2(1.0f, 1.0f);
    const u64 TWOL2 = pack2(2.0f * LOG2E, 2.0f * LOG2E);
    const u64 M2L2  = pack2(-2.0f * LOG2E, -2.0f * LOG2E);

    const float* rowA = state + (size_t)eA  * (size_t)T;
    const float* rowB = state + (size_t)eBc * (size_t)T;

    u64 ccp = 0;                          // packed scaled cell state (A,B)
    float outA = 0.f, outB = 0.f;         // own-unit hidden outputs
    u64 S0 = 0, S1 = 0, S2 = 0;           // packed s1(t-1) broadcasts
    u64 H0 = 0, H1 = 0, H2 = 0;           // packed h2(t-2) broadcasts

    // STEP: one timestep for both elements. 28 ffma2 z; glue f32x2-packed;
    // 10 ex2 + 3 paired rcp.
#define STEP(xa, xb)                                                        \
    do {                                                                    \
        const u64 xab = pack2((xa), (xb));                                  \
        u64 z0 = ffma2(Ap[0], xab, BIp[0]);                                 \
        u64 z1 = ffma2(Ap[1], xab, BIp[1]);                                 \
        u64 z2 = ffma2(Ap[2], xab, BIp[2]);                                 \
        u64 z3 = ffma2(Ap[3], xab, BIp[3]);                                 \
        z0 = ffma2(Bp[0][0], S0, z0); z1 = ffma2(Bp[0][1], S0, z1);         \
        z2 = ffma2(Bp[0][2], S0, z2); z3 = ffma2(Bp[0][3], S0, z3);         \
        z0 = ffma2(Bp[1][0], S1, z0); z1 = ffma2(Bp[1][1], S1, z1);         \
        z2 = ffma2(Bp[1][2], S1, z2); z3 = ffma2(Bp[1][3], S1, z3);         \
        z0 = ffma2(Bp[2][0], S2, z0); z1 = ffma2(Bp[2][1], S2, z1);         \
        z2 = ffma2(Bp[2][2], S2, z2); z3 = ffma2(Bp[2][3], S2, z3);         \
        z0 = ffma2(Cp[0][0], H0, z0); z1 = ffma2(Cp[0][1], H0, z1);         \
        z2 = ffma2(Cp[0][2], H0, z2); z3 = ffma2(Cp[0][3], H0, z3);         \
        z0 = ffma2(Cp[1][0], H1, z0); z1 = ffma2(Cp[1][1], H1, z1);         \
        z2 = ffma2(Cp[1][2], H1, z2); z3 = ffma2(Cp[1][3], H1, z3);         \
        z0 = ffma2(Cp[2][0], H2, z0); z1 = ffma2(Cp[2][1], H2, z1);         \
        z2 = ffma2(Cp[2][2], H2, z2); z3 = ffma2(Cp[2][3], H2, z3);         \
        float zA0, zB0, zA1, zB1, zA2, zB2, zA3, zB3;                       \
        unpack2(z0, zA0, zB0); unpack2(z1, zA1, zB1);                       \
        unpack2(z2, zA2, zB2); unpack2(z3, zA3, zB3);                       \
        const u64 e0p = pack2(fast_ex2(zA0), fast_ex2(zB0));                \
        const u64 e1p = pack2(fast_ex2(zA1), fast_ex2(zB1));                \
        const u64 e2p = pack2(fast_ex2(zA2), fast_ex2(zB2));                \
        const u64 e3p = pack2(fast_ex2(zA3), fast_ex2(zB3));                \
        const u64 d0p = fadd2(e0p, ONE2);                                   \
        const u64 d1p = fadd2(e1p, ONE2);                                   \
        const u64 d2p = fadd2(e2p, ONE2);                                   \
        const u64 d3p = fadd2(e3p, ONE2);                                   \
        const u64 mp  = fmul2(d0p, d2p);                                    \
        float mA, mB, dA1, dB1;                                             \
        unpack2(mp, mA, mB); unpack2(d1p, dA1, dB1);                        \
        const float Rm = fast_rcp(mA * mB);                                 \
        const u64 r02p = pack2(Rm * mB, Rm * mA);                           \
        const float Rf = fast_rcp(dA1 * dB1);                               \
        const u64 sfp  = pack2(Rf * dB1, Rf * dA1);                         \
        const u64 pp   = ffma2(TWOL2, e2p, M2L2);  /* 2L*d2-4L = 2L*e2-2L */\
        const u64 nump = fmul2(pp, r02p);                                   \
        ccp = ffma2(sfp, ccp, nump);                                        \
        float ccA, ccB;                                                     \
        unpack2(ccp, ccA, ccB);                                             \
        const float ecA = fast_ex2(ccA);                                    \
        const float ecB = fast_ex2(ccB);                                    \
        const u64 dcp = fadd2(pack2(ecA, ecB), ONE2);                       \
        const u64 qp  = fmul2(dcp, d3p);                                    \
        float qA, qB;                                                       \
        unpack2(qp, qA, qB);                                                \
        const float Rq = fast_rcp(qA * qB);                                 \
        outA = (1.0f - ecA) * (Rq * qB);                                    \
        outB = (1.0f - ecB) * (Rq * qA);                                    \
    } while (0)

    // exchange: permuted-slot STS.64, one syncwarp, 3x LDS.128
#define XCHG(p)                                                             \
    do {                                                                    \
        xch[(p)][sslot] = pack2(outA, outB);                                \
        __syncwarp(FULLM);                                                  \
        const ulonglong2 v0 =                                               \
            *reinterpret_cast<const ulonglong2*>(&xch[(p)][gbase]);         \
        const ulonglong2 v1 =                                               \
            *reinterpret_cast<const ulonglong2*>(&xch[(p)][gbase + 2]);     \
        const ulonglong2 v2 =                                               \
            *reinterpret_cast<const ulonglong2*>(&xch[(p)][gbase + 4]);     \
        S0 = v0.x; S1 = v0.y; S2 = v1.x;                                    \
        H0 = v1.y; H1 = v2.x; H2 = v2.y;                                    \
    } while (0)

#define BODY(xa, xb, p) do { STEP((xa), (xb)); XCHG(p); } while (0)

    // ---- prologue: t = 0 (L2 lanes reset), then t = 1..3 from first chunk
    float4 a4 = __ldg(reinterpret_cast<const float4*>(rowA));
    float4 b4 = __ldg(reinterpret_cast<const float4*>(rowB));
    float4 nA = a4, nB = b4;
    if (T >= 8) {
        nA = __ldg(reinterpret_cast<const float4*>(rowA + 4));
        nB = __ldg(reinterpret_cast<const float4*>(rowB + 4));
    }

    STEP(a4.x, b4.x);
    if (isL2) { ccp = 0; outA = 0.f; outB = 0.f; }
    XCHG(0);
    BODY(a4.y, b4.y, 1);
    BODY(a4.z, b4.z, 0);
    BODY(a4.w, b4.w, 1);

    int t = 4;
    for (; t + 7 < T; t += 4) {
        a4 = nA; b4 = nB;
        nA = __ldg(reinterpret_cast<const float4*>(rowA + t + 4));
        nB = __ldg(reinterpret_cast<const float4*>(rowB + t + 4));
        BODY(a4.x, b4.x, 0);
        BODY(a4.y, b4.y, 1);
        BODY(a4.z, b4.z, 0);
        BODY(a4.w, b4.w, 1);
    }
    if (t + 3 < T) {                       // final full chunk (already prefetched)
        a4 = nA; b4 = nB;
        BODY(a4.x, b4.x, 0);
        BODY(a4.y, b4.y, 1);
        BODY(a4.z, b4.z, 0);
        BODY(a4.w, b4.w, 1);
        t += 4;
    }
    for (; t < T; ++t) {                   // scalar tail (not taken for T=2048)
        const float xa = __ldg(rowA + t);
        const float xb = __ldg(rowB + t);
        STEP(xa, xb);
        XCHG(t & 1);
    }

    // ---- epilogue: one more step so L2 lanes produce h2(T-1). x unused by
    // L2 (A = 0); L1 lanes' output is never consumed.
    STEP(0.0f, 0.0f);
    xch[0][sslot] = pack2(outA, outB);
    __syncwarp(FULLM);

    if (lane8 == 0 && actA) {
        float f0A, f0B, f1A, f1B, f2A, f2B;
        unpack2(xch[0][gbase + 3], f0A, f0B);   // h2 unit 0 (permuted slots)
        unpack2(xch[0][gbase + 4], f1A, f1B);
        unpack2(xch[0][gbase + 5], f2A, f2B);
        const float w0 = __ldg(Wd + 0), w1 = __ldg(Wd + 1), w2 = __ldg(Wd + 2);
        const float b0 = __ldg(bd);
        out[eA] = fmaf(f2A, w2, fmaf(f1A, w1, fmaf(f0A, w0, b0)));
        if (actB)
            out[eB] = fmaf(f2B, w2, fmaf(f1B, w1, fmaf(f0B, w0, b0)));
    }

#undef STEP
#undef XCHG
#undef BODY
}

extern "C" void kernel_launch(void* const* d_in, const int* in_sizes, int n_in,
                              void* d_out, int out_size)
{
    const float* state = (const float*)d_in[0];
    const float* W1 = (const float*)d_in[1];
    const float* U1 = (const float*)d_in[2];
    const float* b1 = (const float*)d_in[3];
    const float* W2 = (const float*)d_in[4];
    const float* U2 = (const float*)d_in[5];
    const float* b2 = (const float*)d_in[6];
    const float* Wd = (const float*)d_in[7];
    const float* bd = (const float*)d_in[8];
    float* out = (float*)d_out;

    const int B = out_size;            // output is [1, B]
    const int T = in_sizes[0] / B;     // state is [B, T]

    const int pairs = (B + 1) / 2;     // element pair (eA, eA + pairs)
    const int groups_per_warp = 4;     // 4 groups x 8 lanes = 32
    const int blocks = (pairs + groups_per_warp - 1) / groups_per_warp;
    lstm2_r8_kernel<<<blocks, 32>>>(state, W1, U1, b1, W2, U2, b2,
                                    Wd, bd, out, B, T, pairs);
}

// round 9
// speedup vs baseline: 1.2154x; 1.0388x over previous
#include <cuda_runtime.h>

// LSTMBrain: 2-layer LSTM (hidden=3) over [B=4096, T=2048], dense head 3->1.
// Round 9: phase-overlap design. 8 lanes per SINGLE element (lane8 0-2: L1
// units, 4-6: L2 units, 3/7 dup), 4 elements/warp -> 1024 warps (~2/SMSP):
// two warps interleave their serial step-phases (z-FMA / MUFU burst / smem
// exchange) on each SMSP, filling each other's stalls. Per-warp cost cut:
//  - z packed as gate-pairs (i,f) & (g,o) in fma.rn.f32x2: 14 ffma2.
//  - 7 MUFU/step: 4 gate ex2 + 1 cell ex2 + rcp(d0*d2*d1) + rcp(dc*d3).
//  - exchange: STS.64 of (outv,outv) into permuted slots, syncwarp, then
//    3x LDS.128 returning S0..S2/H0..H2 already duplicated for f32x2 use.
// L2 lags L1 by one step as before (unified coefficient form, A=0 for L2).

typedef unsigned long long u64;

#define FULLM 0xFFFFFFFFu
#define LOG2E 1.4426950408889634f

__device__ __forceinline__ float fast_rcp(float x) {
    float r; asm("rcp.approx.f32 %0, %1;" : "=f"(r) : "f"(x)); return r;
}
__device__ __forceinline__ float fast_ex2(float x) {
    float r; asm("ex2.approx.f32 %0, %1;" : "=f"(r) : "f"(x)); return r;
}
__device__ __forceinline__ u64 ffma2(u64 a, u64 b, u64 c) {
    u64 d; asm("fma.rn.f32x2 %0, %1, %2, %3;" : "=l"(d) : "l"(a), "l"(b), "l"(c));
    return d;
}
__device__ __forceinline__ u64 pack2(float lo, float hi) {
    u64 d; asm("mov.b64 %0, {%1, %2};" : "=l"(d) : "f"(lo), "f"(hi)); return d;
}
__device__ __forceinline__ void unpack2(u64 v, float& lo, float& hi) {
    asm("mov.b64 {%0, %1}, %2;" : "=f"(lo), "=f"(hi) : "l"(v));
}

__global__ void __launch_bounds__(32, 1) lstm2_r9_kernel(
    const float* __restrict__ state,
    const float* __restrict__ W1, const float* __restrict__ U1, const float* __restrict__ b1,
    const float* __restrict__ W2, const float* __restrict__ U2, const float* __restrict__ b2,
    const float* __restrict__ Wd, const float* __restrict__ bd,
    float* __restrict__ out, int B, int T)
{
    __shared__ __align__(16) u64 xch[2][32];   // [buffer][slot], (v,v) dup

    const int lane  = threadIdx.x & 31;
    const int lane8 = lane & 7;
    const int gbase = lane & ~7;               // group's first lane/slot
    const int sub   = lane8 & 3;
    const int u     = (sub < 3) ? sub : 2;     // owned hidden unit (3/7 dup 2)
    const bool isL2 = (lane8 & 4) != 0;
    // permuted write slot: roles 0,1,2 -> 0,1,2 ; 4,5,6 -> 3,4,5 ; 3->6, 7->7
    const int sslot = gbase + ((lane8 < 3) ? lane8
                        : (lane8 == 3) ? 6
                        : (lane8 < 7) ? (lane8 - 1) : 7);

    int e = blockIdx.x * 4 + (lane >> 3);      // element of this group
    const bool act = (e < B);
    if (!act) e = B - 1;

    // ---- gate-pair packed coefficients, pre-scaled into the ex2 domain ----
    // pair P0 = gates (i, f), pair P1 = gates (g, o); column(gate) = gate*3+u
    // sigma gates scaled by -log2e, tanh gate by -2log2e (folded into weights)
    u64 AP[2], BIP[2], BP[3][2], CP[3][2];
#pragma unroll
    for (int pr = 0; pr < 2; ++pr) {
        const int glo = (pr == 0) ? 0 : 2;     // gate of lo half (i or g)
        const int ghi = (pr == 0) ? 1 : 3;     // gate of hi half (f or o)
        const int clo = glo * 3 + u, chi = ghi * 3 + u;
        const float slo = (glo == 2) ? (-2.0f * LOG2E) : (-LOG2E);
        const float shi = -LOG2E;              // f and o are sigmoids
        if (isL2) {
            AP[pr]  = 0;
            BIP[pr] = pack2(__ldg(b2 + clo) * slo, __ldg(b2 + chi) * shi);
#pragma unroll
            for (int k = 0; k < 3; ++k) {
                BP[k][pr] = pack2(__ldg(W2 + k * 12 + clo) * slo,
                                  __ldg(W2 + k * 12 + chi) * shi);  // * s1
                CP[k][pr] = pack2(__ldg(U2 + k * 12 + clo) * slo,
                                  __ldg(U2 + k * 12 + chi) * shi);  // * h2
            }
        } else {
            AP[pr]  = pack2(__ldg(W1 + clo) * slo, __ldg(W1 + chi) * shi);
            BIP[pr] = pack2(__ldg(b1 + clo) * slo, __ldg(b1 + chi) * shi);
#pragma unroll
            for (int k = 0; k < 3; ++k) {
                BP[k][pr] = pack2(__ldg(U1 + k * 12 + clo) * slo,
                                  __ldg(U1 + k * 12 + chi) * shi);  // * s1
                CP[k][pr] = 0;
            }
        }
    }

    const float* xrow = state + (size_t)e * (size_t)T;

    float cc   = 0.f;                     // own-unit scaled cell state
    float outv = 0.f;                     // own-unit hidden output
    u64 S0 = 0, S1 = 0, S2 = 0;           // duplicated s1(t-1) broadcasts
    u64 H0 = 0, H1 = 0, H2 = 0;           // duplicated h2(t-2) broadcasts

    // STEP: one timestep. 14 ffma2 z, 7 MUFU, ~15 scalar glue.
#define STEP(xv)                                                            \
    do {                                                                    \
        const u64 xp = pack2((xv), (xv));                                   \
        u64 za = ffma2(AP[0], xp, BIP[0]);                                  \
        u64 zb = ffma2(AP[1], xp, BIP[1]);                                  \
        za = ffma2(BP[0][0], S0, za); zb = ffma2(BP[0][1], S0, zb);         \
        za = ffma2(BP[1][0], S1, za); zb = ffma2(BP[1][1], S1, zb);         \
        za = ffma2(BP[2][0], S2, za); zb = ffma2(BP[2][1], S2, zb);         \
        za = ffma2(CP[0][0], H0, za); zb = ffma2(CP[0][1], H0, zb);         \
        za = ffma2(CP[1][0], H1, za); zb = ffma2(CP[1][1], H1, zb);         \
        za = ffma2(CP[2][0], H2, za); zb = ffma2(CP[2][1], H2, zb);         \
        float zi, zf, zg, zo;                                               \
        unpack2(za, zi, zf); unpack2(zb, zg, zo);                           \
        const float ei = fast_ex2(zi);                                      \
        const float ef = fast_ex2(zf);                                      \
        const float eg = fast_ex2(zg);                                      \
        const float eo = fast_ex2(zo);                                      \
        const float di = 1.0f + ei, df = 1.0f + ef;                         \
        const float dg = 1.0f + eg, dq = 1.0f + eo;                         \
        const float m  = di * dg;                                           \
        const float Rm = fast_rcp(m * df);                                  \
        const float sf  = Rm * m;     /* 1/df */                            \
        const float r02 = Rm * df;    /* 1/(di*dg) */                       \
        /* p = -2L*tanh_g numerator scaled: 2L*eg - 2L */                   \
        const float p = fmaf(2.0f * LOG2E, eg, -2.0f * LOG2E);              \
        cc = fmaf(sf, cc, p * r02);                                         \
        const float ec = fast_ex2(cc);                                      \
        const float dc = 1.0f + ec;                                         \
        const float Rq = fast_rcp(dc * dq);                                 \
        outv = (1.0f - ec) * Rq;      /* tanh(c) * sigmoid(o) */            \
    } while (0)

    // exchange: duplicated STS.64, one syncwarp, 3x LDS.128
#define XCHG(p)                                                             \
    do {                                                                    \
        xch[(p)][sslot] = pack2(outv, outv);                                \
        __syncwarp(FULLM);                                                  \
        const ulonglong2 v0 =                                               \
            *reinterpret_cast<const ulonglong2*>(&xch[(p)][gbase]);         \
        const ulonglong2 v1 =                                               \
            *reinterpret_cast<const ulonglong2*>(&xch[(p)][gbase + 2]);     \
        const ulonglong2 v2 =                                               \
            *reinterpret_cast<const ulonglong2*>(&xch[(p)][gbase + 4]);     \
        S0 = v0.x; S1 = v0.y; S2 = v1.x;                                    \
        H0 = v1.y; H1 = v2.x; H2 = v2.y;                                    \
    } while (0)

#define BODY(xv, p) do { STEP(xv); XCHG(p); } while (0)

    // ---- prologue: t = 0 (L2 lanes reset), then t = 1..3 from first chunk
    float4 a4 = __ldg(reinterpret_cast<const float4*>(xrow));
    float4 nA = a4;
    if (T >= 8) nA = __ldg(reinterpret_cast<const float4*>(xrow + 4));

    STEP(a4.x);
    if (isL2) { cc = 0.f; outv = 0.f; }
    XCHG(0);
    BODY(a4.y, 1);
    BODY(a4.z, 0);
    BODY(a4.w, 1);

    int t = 4;
    for (; t + 7 < T; t += 4) {
        a4 = nA;
        nA = __ldg(reinterpret_cast<const float4*>(xrow + t + 4));
        BODY(a4.x, 0);
        BODY(a4.y, 1);
        BODY(a4.z, 0);
        BODY(a4.w, 1);
    }
    if (t + 3 < T) {                      // last full chunk (already prefetched)
        a4 = nA;
        BODY(a4.x, 0);
        BODY(a4.y, 1);
        BODY(a4.z, 0);
        BODY(a4.w, 1);
        t += 4;
    }
    for (; t < T; ++t) {                  // scalar tail (not taken for T=2048)
        BODY(__ldg(xrow + t), t & 1);
    }

    // ---- epilogue: one more step so L2 lanes produce h2(T-1). x unused by
    // L2 (A = 0); L1 lanes' output is never consumed.
    STEP(0.0f);
    xch[0][sslot] = pack2(outv, outv);
    __syncwarp(FULLM);

    if (lane8 == 0 && act) {
        float f0, f1, f2, junk;
        unpack2(xch[0][gbase + 3], f0, junk);   // h2 unit 0 (permuted slots)
        unpack2(xch[0][gbase + 4], f1, junk);
        unpack2(xch[0][gbase + 5], f2, junk);
        float r = __ldg(bd);
        r = fmaf(f0, __ldg(Wd + 0), r);
        r = fmaf(f1, __ldg(Wd + 1), r);
        r = fmaf(f2, __ldg(Wd + 2), r);
        out[e] = r;
    }

#undef STEP
#undef XCHG
#undef BODY
}

extern "C" void kernel_launch(void* const* d_in, const int* in_sizes, int n_in,
                              void* d_out, int out_size)
{
    const float* state = (const float*)d_in[0];
    const float* W1 = (const float*)d_in[1];
    const float* U1 = (const float*)d_in[2];
    const float* b1 = (const float*)d_in[3];
    const float* W2 = (const float*)d_in[4];
    const float* U2 = (const float*)d_in[5];
    const float* b2 = (const float*)d_in[6];
    const float* Wd = (const float*)d_in[7];
    const float* bd = (const float*)d_in[8];
    float* out = (float*)d_out;

    const int B = out_size;            // output is [1, B]
    const int T = in_sizes[0] / B;     // state is [B, T]

    const int elems_per_warp = 4;      // 4 groups x 8 lanes = 32
    const int blocks = (B + elems_per_warp - 1) / elems_per_warp;   // 1024
    lstm2_r9_kernel<<<blocks, 32>>>(state, W1, U1, b1, W2, U2, b2,
                                    Wd, bd, out, B, T);
}